// round 14
// baseline (speedup 1.0000x reference)
#include <cuda_runtime.h>
#include <cuda_fp16.h>
#include <math_constants.h>
#include <cstdint>

#define N_NODES 100000
#define D_MODEL 256
#define N_SLOTS 512
#define TILE_M 32
#define THREADS 256
#define N_TILES (N_NODES / TILE_M)   // 3125 exactly
#define CTAS_PER_BANK 152
#define LOG2E_F 1.4426950408889634f

// smem byte offsets
#define OFF_QH 0          // 16KB  (GEMM1 A hi)
#define OFF_QL 16384      // 16KB  (GEMM1 A lo)
#define OFF_PH 0          // 32KB  (GEMM2 A hi — overlays QH+QL)
#define OFF_LMAX 32768    // 1KB [32][8]
#define OFF_LSUM 33792    // 1KB
#define SMEM_BYTES 34816

// Pre-packed B fragments for mma.sync.m16n8k16.row.col (4 halfs per lane, uint2).
// G1B[mem][split][kt(16)][nt(64)][lane(32)] : B = (M*log2e)^T  (k=dmodel, n=slot)
// G2B[mem][kt(32)][nt(32)][lane(32)]        : B = M hi         (k=slot,  n=dmodel)
__device__ __align__(16) uint2 G1B[2][2][16][64][32];
__device__ __align__(16) uint2 G2B[2][32][32][32];

__device__ __forceinline__ void split2h(float x, float y, uint32_t& hi, uint32_t& lo) {
    __half hx = __float2half_rn(x);
    __half hy = __float2half_rn(y);
    __half lx = __float2half_rn(x - __half2float(hx));
    __half ly = __float2half_rn(y - __half2float(hy));
    __half2 h = __halves2half2(hx, hy);
    __half2 l = __halves2half2(lx, ly);
    hi = *(uint32_t*)&h;
    lo = *(uint32_t*)&l;
}

__device__ __forceinline__ uint32_t pack2h(float x, float y) {
    __half2 h = __halves2half2(__float2half_rn(x), __float2half_rn(y));
    return *(uint32_t*)&h;
}

__device__ __forceinline__ float ex2(float x) {
    float r;
    asm("ex2.approx.f32 %0, %1;" : "=f"(r) : "f"(x));
    return r;
}

__device__ __forceinline__ void mma16816(float* c, const uint4& a, const uint2& b) {
    asm volatile(
        "mma.sync.aligned.m16n8k16.row.col.f32.f16.f16.f32 "
        "{%0,%1,%2,%3}, {%4,%5,%6,%7}, {%8,%9}, {%0,%1,%2,%3};"
        : "+f"(c[0]), "+f"(c[1]), "+f"(c[2]), "+f"(c[3])
        : "r"(a.x), "r"(a.y), "r"(a.z), "r"(a.w), "r"(b.x), "r"(b.y));
}

// ---------------- prep: pack memory matrices into B-fragment order ----------------
__global__ void prep_kernel(const float* __restrict__ ma, const float* __restrict__ ms) {
    int idx = blockIdx.x * blockDim.x + threadIdx.x;
    if (idx >= 131072) return;
    bool isG2 = idx >= 65536;
    int r = idx & 65535;
    int lane = r & 31;
    int t = lane & 3, g = lane >> 2;
    if (!isG2) {
        int nt = (r >> 5) & 63;
        int kt = (r >> 11) & 15;
        int mem = (r >> 15) & 1;
        const float* src = mem ? ms : ma;
        int slot = nt * 8 + g;
        int k = kt * 16 + 2 * t;
        float v0 = src[slot * D_MODEL + k]     * LOG2E_F;
        float v1 = src[slot * D_MODEL + k + 1] * LOG2E_F;
        float v2 = src[slot * D_MODEL + k + 8] * LOG2E_F;
        float v3 = src[slot * D_MODEL + k + 9] * LOG2E_F;
        uint32_t h01, l01, h23, l23;
        split2h(v0, v1, h01, l01);
        split2h(v2, v3, h23, l23);
        G1B[mem][0][kt][nt][lane] = make_uint2(h01, h23);
        G1B[mem][1][kt][nt][lane] = make_uint2(l01, l23);
    } else {
        int nt = (r >> 5) & 31;
        int kt = (r >> 10) & 31;
        int mem = (r >> 15) & 1;
        const float* src = mem ? ms : ma;
        int col = nt * 8 + g;
        int ks = kt * 16 + 2 * t;
        float v0 = src[(ks)     * D_MODEL + col];
        float v1 = src[(ks + 1) * D_MODEL + col];
        float v2 = src[(ks + 8) * D_MODEL + col];
        float v3 = src[(ks + 9) * D_MODEL + col];
        G2B[mem][kt][nt][lane] = make_uint2(pack2h(v0, v1), pack2h(v2, v3));
    }
}

// ---------------- main persistent kernel (2 CTAs/SM, 8 warps each) ----------------
__global__ __launch_bounds__(THREADS, 2)
void smgt_hmma(const float* __restrict__ query, float* __restrict__ out) {
    extern __shared__ char smem[];
    const int tid = threadIdx.x;
    const int w = tid >> 5, lane = tid & 31;
    const int t = lane & 3, g = lane >> 2;
    const int memi = (blockIdx.x >= CTAS_PER_BANK) ? 1 : 0;
    const int cta = blockIdx.x - memi * CTAS_PER_BANK;   // 0..151
    float* __restrict__ outg = out + (size_t)memi * N_NODES * 512u;

    float* lmaxs = (float*)(smem + OFF_LMAX);   // [32][8]
    float* lsums = (float*)(smem + OFF_LSUM);

    // persistent half-period stagger for bank-1 CTAs (likely second slot on each SM)
    if (memi) {
        long long s0 = clock64();
        while (clock64() - s0 < 21700) {}
    }

    // ---- prefetch Q for first tile ----
    int tile = cta;
    float4 q[8];
    {
        int n0 = tile * TILE_M;
        #pragma unroll
        for (int it = 0; it < 8; it++) {
            int idx = tid + it * THREADS;
            int rr = idx >> 6, c4 = idx & 63;
            q[it] = ((const float4*)query)[(size_t)(n0 + rr) * 64 + c4];
        }
    }

    #pragma unroll 1
    for (; tile < N_TILES; tile += CTAS_PER_BANK) {
        const int n0 = tile * TILE_M;

        // ---- split Q (from prefetched regs) into A-frag smem; fuse Q-copy out ----
        #pragma unroll
        for (int it = 0; it < 8; it++) {
            int idx = tid + it * THREADS;
            int rr = idx >> 6, c4 = idx & 63;
            int gr = n0 + rr;
            float4 v = q[it];
            ((float4*)outg)[(size_t)gr * 128 + c4] = v;
            int mt = rr >> 4, sr = rr & 15, gg = sr & 7, hr = sr >> 3;
            #pragma unroll
            for (int p = 0; p < 2; p++) {
                int k = c4 * 4 + 2 * p;
                int kt = k >> 4, sk = k & 15;
                int ln = gg * 4 + ((sk & 7) >> 1);
                int off = ((kt * 2 + mt) * 32 + (ln ^ (kt & 7))) * 16 + 4 * hr + 8 * (sk >> 3);
                float x = p ? v.z : v.x;
                float y = p ? v.w : v.y;
                uint32_t hi, lo;
                split2h(x, y, hi, lo);
                *(uint32_t*)(smem + OFF_QH + off) = hi;
                *(uint32_t*)(smem + OFF_QL + off) = lo;
            }
        }
        __syncthreads();   // QH/QL visible

        // ============ GEMM1: S' = Q @ (M*log2e)^T (32x512, warp = 32x64) ============
        float acc[2][8][4];
        #pragma unroll
        for (int mt = 0; mt < 2; mt++)
            #pragma unroll
            for (int j = 0; j < 8; j++)
                #pragma unroll
                for (int i = 0; i < 4; i++) acc[mt][j][i] = 0.f;

        {
            const uint2* __restrict__ g1h = &G1B[memi][0][0][w * 8][0];
            const uint2* __restrict__ g1l = &G1B[memi][1][0][w * 8][0];
            uint2 bh[2][4], bl[2][4];
            #pragma unroll
            for (int j = 0; j < 4; j++) {
                bh[0][j] = g1h[j * 32 + lane];
                bl[0][j] = g1l[j * 32 + lane];
            }

            #pragma unroll 1
            for (int kt = 0; kt < 16; kt++) {
                uint4 ah[2], al[2];
                #pragma unroll
                for (int mt = 0; mt < 2; mt++) {
                    int chunk = ((kt * 2 + mt) * 32 + (lane ^ (kt & 7))) * 16;
                    ah[mt] = *(const uint4*)(smem + OFF_QH + chunk);
                    al[mt] = *(const uint4*)(smem + OFF_QL + chunk);
                }
                // half h=0: prefetch (kt, h=1) -> buf1, compute buf0
                {
                    int base = kt * 2048 + 128 + lane;
                    #pragma unroll
                    for (int j = 0; j < 4; j++) {
                        bh[1][j] = g1h[base + j * 32];
                        bl[1][j] = g1l[base + j * 32];
                    }
                    #pragma unroll
                    for (int j = 0; j < 4; j++)
                        #pragma unroll
                        for (int mt = 0; mt < 2; mt++) {
                            mma16816(acc[mt][j], ah[mt], bh[0][j]);
                            mma16816(acc[mt][j], al[mt], bh[0][j]);
                            mma16816(acc[mt][j], ah[mt], bl[0][j]);
                        }
                }
                // half h=1: prefetch (kt+1, h=0) -> buf0, compute buf1
                {
                    if (kt + 1 < 16) {
                        int base = (kt + 1) * 2048 + lane;
                        #pragma unroll
                        for (int j = 0; j < 4; j++) {
                            bh[0][j] = g1h[base + j * 32];
                            bl[0][j] = g1l[base + j * 32];
                        }
                    }
                    #pragma unroll
                    for (int j = 0; j < 4; j++)
                        #pragma unroll
                        for (int mt = 0; mt < 2; mt++) {
                            mma16816(acc[mt][4 + j], ah[mt], bh[1][j]);
                            mma16816(acc[mt][4 + j], al[mt], bh[1][j]);
                            mma16816(acc[mt][4 + j], ah[mt], bl[1][j]);
                        }
                }
            }
        }

        // ============ softmax (base-2, single block sync) ============
        float lmax[2][2];
        #pragma unroll
        for (int mt = 0; mt < 2; mt++)
            #pragma unroll
            for (int i2 = 0; i2 < 2; i2++) {
                float m = -CUDART_INF_F;
                #pragma unroll
                for (int j = 0; j < 8; j++) {
                    m = fmaxf(m, acc[mt][j][2 * i2]);
                    m = fmaxf(m, acc[mt][j][2 * i2 + 1]);
                }
                m = fmaxf(m, __shfl_xor_sync(0xffffffffu, m, 1));
                m = fmaxf(m, __shfl_xor_sync(0xffffffffu, m, 2));
                lmax[mt][i2] = m;
                float s = 0.f;
                #pragma unroll
                for (int j = 0; j < 8; j++) {
                    float e0 = ex2(acc[mt][j][2 * i2]     - m);
                    float e1 = ex2(acc[mt][j][2 * i2 + 1] - m);
                    acc[mt][j][2 * i2]     = e0;
                    acc[mt][j][2 * i2 + 1] = e1;
                    s += e0 + e1;
                }
                s += __shfl_xor_sync(0xffffffffu, s, 1);
                s += __shfl_xor_sync(0xffffffffu, s, 2);
                if (t == 0) {
                    lmaxs[(mt * 16 + g + 8 * i2) * 8 + w] = m;
                    lsums[(mt * 16 + g + 8 * i2) * 8 + w] = s;
                }
            }
        __syncthreads();   // stats visible

        float scale[2][2], inv[2][2];
        #pragma unroll
        for (int mt = 0; mt < 2; mt++)
            #pragma unroll
            for (int i2 = 0; i2 < 2; i2++) {
                int row = mt * 16 + g + 8 * i2;
                const float* Lm = &lmaxs[row * 8];
                const float* Ls = &lsums[row * 8];
                float gm = Lm[0];
                #pragma unroll
                for (int j = 1; j < 8; j++) gm = fmaxf(gm, Lm[j]);
                float gs = 0.f;
                #pragma unroll
                for (int j = 0; j < 8; j++) gs += Ls[j] * ex2(Lm[j] - gm);
                scale[mt][i2] = ex2(lmax[mt][i2] - gm) * 16384.f;
                inv[mt][i2] = 1.f / (gs * 16384.f);
            }

        // ---- pack P hi into GEMM2 A layout (overwrites QH/QL region) ----
        #pragma unroll
        for (int mt = 0; mt < 2; mt++)
            #pragma unroll
            for (int j = 0; j < 8; j++) {
                int kt2 = w * 4 + (j >> 1);
                int base = OFF_PH + ((kt2 * 2 + mt) * 32 + (lane ^ (kt2 & 7))) * 16 + 8 * (j & 1);
                *(uint32_t*)(smem + base)     = pack2h(acc[mt][j][0] * scale[mt][0],
                                                       acc[mt][j][1] * scale[mt][0]);
                *(uint32_t*)(smem + base + 4) = pack2h(acc[mt][j][2] * scale[mt][1],
                                                       acc[mt][j][3] * scale[mt][1]);
            }
        __syncthreads();   // PH visible

        // ---- issue next-tile Q prefetch (hidden under GEMM2 MMAs) ----
        {
            int ntile = tile + CTAS_PER_BANK;
            if (ntile < N_TILES) {
                int nn0 = ntile * TILE_M;
                #pragma unroll
                for (int it = 0; it < 8; it++) {
                    int idx = tid + it * THREADS;
                    int rr = idx >> 6, c4 = idx & 63;
                    q[it] = ((const float4*)query)[(size_t)(nn0 + rr) * 64 + c4];
                }
            }
        }

        // ============ GEMM2: R = P @ M (32x256, warp = 32x32, 1-term) ============
        float a2[2][4][4];
        #pragma unroll
        for (int mt = 0; mt < 2; mt++)
            #pragma unroll
            for (int j = 0; j < 4; j++)
                #pragma unroll
                for (int i = 0; i < 4; i++) a2[mt][j][i] = 0.f;

        {
            const uint2* __restrict__ g2h = &G2B[memi][0][w * 4][0];
            uint2 ch[2][4];
            #pragma unroll
            for (int j = 0; j < 4; j++) ch[0][j] = g2h[j * 32 + lane];

            #pragma unroll 1
            for (int kp = 0; kp < 16; kp++) {
                // kt = 2*kp (buf0), prefetch kt+1 -> buf1
                {
                    int kt = 2 * kp;
                    uint4 ph[2];
                    #pragma unroll
                    for (int mt = 0; mt < 2; mt++) {
                        int chunk = OFF_PH + ((kt * 2 + mt) * 32 + (lane ^ (kt & 7))) * 16;
                        ph[mt] = *(const uint4*)(smem + chunk);
                    }
                    int base = (kt + 1) * 1024 + lane;
                    #pragma unroll
                    for (int j = 0; j < 4; j++) ch[1][j] = g2h[base + j * 32];
                    #pragma unroll
                    for (int j = 0; j < 4; j++)
                        #pragma unroll
                        for (int mt = 0; mt < 2; mt++)
                            mma16816(a2[mt][j], ph[mt], ch[0][j]);
                }
                // kt = 2*kp+1 (buf1), prefetch kt+1 -> buf0
                {
                    int kt = 2 * kp + 1;
                    uint4 ph[2];
                    #pragma unroll
                    for (int mt = 0; mt < 2; mt++) {
                        int chunk = OFF_PH + ((kt * 2 + mt) * 32 + (lane ^ (kt & 7))) * 16;
                        ph[mt] = *(const uint4*)(smem + chunk);
                    }
                    if (kt + 1 < 32) {
                        int base = (kt + 1) * 1024 + lane;
                        #pragma unroll
                        for (int j = 0; j < 4; j++) ch[0][j] = g2h[base + j * 32];
                    }
                    #pragma unroll
                    for (int j = 0; j < 4; j++)
                        #pragma unroll
                        for (int mt = 0; mt < 2; mt++)
                            mma16816(a2[mt][j], ph[mt], ch[1][j]);
                }
            }
        }

        // ---- epilogue: scale by 1/(gsum*2^14), store R half ----
        #pragma unroll
        for (int mt = 0; mt < 2; mt++)
            #pragma unroll
            for (int j = 0; j < 4; j++) {
                int col = w * 32 + j * 8 + 2 * t;
                #pragma unroll
                for (int i2 = 0; i2 < 2; i2++) {
                    int gr = n0 + mt * 16 + g + 8 * i2;
                    float2 o;
                    o.x = a2[mt][j][2 * i2]     * inv[mt][i2];
                    o.y = a2[mt][j][2 * i2 + 1] * inv[mt][i2];
                    *(float2*)&outg[(size_t)gr * 512 + 256 + col] = o;
                }
            }

        __syncthreads();   // all PH reads done before next tile's split overwrites it
    }
}

extern "C" void kernel_launch(void* const* d_in, const int* in_sizes, int n_in,
                              void* d_out, int out_size) {
    const float* query      = (const float*)d_in[0];
    const float* mem_attr   = (const float*)d_in[1];
    const float* mem_struct = (const float*)d_in[2];
    float* out = (float*)d_out;

    prep_kernel<<<512, 256>>>(mem_attr, mem_struct);

    cudaFuncSetAttribute(smgt_hmma, cudaFuncAttributeMaxDynamicSharedMemorySize, SMEM_BYTES);
    smgt_hmma<<<2 * CTAS_PER_BANK, THREADS, SMEM_BYTES>>>(query, out);
}

// round 15
// speedup vs baseline: 1.1907x; 1.1907x over previous
#include <cuda_runtime.h>
#include <cuda_fp16.h>
#include <math_constants.h>
#include <cstdint>

#define N_NODES 100000
#define D_MODEL 256
#define N_SLOTS 512
#define TILE_M 32
#define THREADS 256
#define N_TILES (N_NODES / TILE_M)   // 3125 exactly
#define LOG2E_F 1.4426950408889634f

// smem byte offsets
#define OFF_QH 0          // 16KB  (GEMM1 A hi)
#define OFF_QL 16384      // 16KB  (GEMM1 A lo)
#define OFF_PH 0          // 32KB  (GEMM2 A hi — overlays QH+QL)
#define OFF_LMAX 32768    // 1KB [32][8]
#define OFF_LSUM 33792    // 1KB
#define SMEM_BYTES 34816

// Pre-packed B fragments for mma.sync.m16n8k16.row.col (4 halfs per lane, uint2).
// G1B[mem][split][kt(16)][nt(64)][lane(32)] : B = (M*log2e)^T  (k=dmodel, n=slot)
// G2B[mem][kt(32)][nt(32)][lane(32)]        : B = M hi         (k=slot,  n=dmodel)
__device__ __align__(16) uint2 G1B[2][2][16][64][32];
__device__ __align__(16) uint2 G2B[2][32][32][32];

__device__ __forceinline__ void split2h(float x, float y, uint32_t& hi, uint32_t& lo) {
    __half hx = __float2half_rn(x);
    __half hy = __float2half_rn(y);
    __half lx = __float2half_rn(x - __half2float(hx));
    __half ly = __float2half_rn(y - __half2float(hy));
    __half2 h = __halves2half2(hx, hy);
    __half2 l = __halves2half2(lx, ly);
    hi = *(uint32_t*)&h;
    lo = *(uint32_t*)&l;
}

__device__ __forceinline__ uint32_t pack2h(float x, float y) {
    __half2 h = __halves2half2(__float2half_rn(x), __float2half_rn(y));
    return *(uint32_t*)&h;
}

__device__ __forceinline__ float ex2(float x) {
    float r;
    asm("ex2.approx.f32 %0, %1;" : "=f"(r) : "f"(x));
    return r;
}

__device__ __forceinline__ void mma16816(float* c, const uint4& a, const uint2& b) {
    asm volatile(
        "mma.sync.aligned.m16n8k16.row.col.f32.f16.f16.f32 "
        "{%0,%1,%2,%3}, {%4,%5,%6,%7}, {%8,%9}, {%0,%1,%2,%3};"
        : "+f"(c[0]), "+f"(c[1]), "+f"(c[2]), "+f"(c[3])
        : "r"(a.x), "r"(a.y), "r"(a.z), "r"(a.w), "r"(b.x), "r"(b.y));
}

// ---------------- prep: pack memory matrices into B-fragment order ----------------
__global__ void prep_kernel(const float* __restrict__ ma, const float* __restrict__ ms) {
    int idx = blockIdx.x * blockDim.x + threadIdx.x;
    if (idx >= 131072) return;
    bool isG2 = idx >= 65536;
    int r = idx & 65535;
    int lane = r & 31;
    int t = lane & 3, g = lane >> 2;
    if (!isG2) {
        int nt = (r >> 5) & 63;
        int kt = (r >> 11) & 15;
        int mem = (r >> 15) & 1;
        const float* src = mem ? ms : ma;
        int slot = nt * 8 + g;
        int k = kt * 16 + 2 * t;
        float v0 = src[slot * D_MODEL + k]     * LOG2E_F;
        float v1 = src[slot * D_MODEL + k + 1] * LOG2E_F;
        float v2 = src[slot * D_MODEL + k + 8] * LOG2E_F;
        float v3 = src[slot * D_MODEL + k + 9] * LOG2E_F;
        uint32_t h01, l01, h23, l23;
        split2h(v0, v1, h01, l01);
        split2h(v2, v3, h23, l23);
        G1B[mem][0][kt][nt][lane] = make_uint2(h01, h23);
        G1B[mem][1][kt][nt][lane] = make_uint2(l01, l23);
    } else {
        int nt = (r >> 5) & 31;
        int kt = (r >> 10) & 31;
        int mem = (r >> 15) & 1;
        const float* src = mem ? ms : ma;
        int col = nt * 8 + g;
        int ks = kt * 16 + 2 * t;
        float v0 = src[(ks)     * D_MODEL + col];
        float v1 = src[(ks + 1) * D_MODEL + col];
        float v2 = src[(ks + 8) * D_MODEL + col];
        float v3 = src[(ks + 9) * D_MODEL + col];
        G2B[mem][kt][nt][lane] = make_uint2(pack2h(v0, v1), pack2h(v2, v3));
    }
}

// ---------------- main fused kernel (2 CTAs/SM, 8 warps each) ----------------
__global__ __launch_bounds__(THREADS, 2)
void smgt_hmma(const float* __restrict__ query, float* __restrict__ out) {
    extern __shared__ char smem[];
    const int tid = threadIdx.x;
    const int w = tid >> 5, lane = tid & 31;
    const int t = lane & 3, g = lane >> 2;
    const int memi = blockIdx.y;
    const int n0 = blockIdx.x * TILE_M;
    float* __restrict__ outg = out + (size_t)memi * N_NODES * 512u;

    // ---- load Q tile, split fp16 hi/lo, store A-fragment-packed; fuse Q-copy out ----
    #pragma unroll 4
    for (int it = 0; it < 8; it++) {
        int idx = tid + it * THREADS;    // 0..2047 float4s
        int rr = idx >> 6;               // row 0..31
        int c4 = idx & 63;
        int gr = n0 + rr;                // always < N_NODES (3125*32 = 100000)
        float4 v = ((const float4*)query)[(size_t)gr * 64 + c4];
        __stcs(((float4*)outg) + (size_t)gr * 128 + c4, v);   // Q copy (streaming)
        int mt = rr >> 4, sr = rr & 15, gg = sr & 7, hr = sr >> 3;
        #pragma unroll
        for (int p = 0; p < 2; p++) {
            int k = c4 * 4 + 2 * p;
            int kt = k >> 4, sk = k & 15;
            int ln = gg * 4 + ((sk & 7) >> 1);
            int off = ((kt * 2 + mt) * 32 + (ln ^ (kt & 7))) * 16 + 4 * hr + 8 * (sk >> 3);
            float x = p ? v.z : v.x;
            float y = p ? v.w : v.y;
            uint32_t hi, lo;
            split2h(x, y, hi, lo);
            *(uint32_t*)(smem + OFF_QH + off) = hi;
            *(uint32_t*)(smem + OFF_QL + off) = lo;
        }
    }
    __syncthreads();

    // ================= GEMM1: S' = Q @ (M*log2e)^T (32x512, warp = 32x64) ==========
    float acc[2][8][4];
    #pragma unroll
    for (int mt = 0; mt < 2; mt++)
        #pragma unroll
        for (int j = 0; j < 8; j++)
            #pragma unroll
            for (int i = 0; i < 4; i++) acc[mt][j][i] = 0.f;

    {
        const uint2* __restrict__ g1h = &G1B[memi][0][0][w * 8][0];
        const uint2* __restrict__ g1l = &G1B[memi][1][0][w * 8][0];
        // element (kt, h, j): kt*2048 + (h*4+j)*32 + lane   (uint2 units)
        uint2 bh[2][4], bl[2][4];
        #pragma unroll
        for (int j = 0; j < 4; j++) {
            bh[0][j] = g1h[j * 32 + lane];
            bl[0][j] = g1l[j * 32 + lane];
        }

        #pragma unroll 1
        for (int kt = 0; kt < 16; kt++) {
            uint4 ah[2], al[2];
            #pragma unroll
            for (int mt = 0; mt < 2; mt++) {
                int chunk = ((kt * 2 + mt) * 32 + (lane ^ (kt & 7))) * 16;
                ah[mt] = *(const uint4*)(smem + OFF_QH + chunk);
                al[mt] = *(const uint4*)(smem + OFF_QL + chunk);
            }

            // ---- half h=0: prefetch (kt, h=1) -> buf1, compute buf0 ----
            {
                int base = kt * 2048 + 128 + lane;
                #pragma unroll
                for (int j = 0; j < 4; j++) {
                    bh[1][j] = g1h[base + j * 32];
                    bl[1][j] = g1l[base + j * 32];
                }
                #pragma unroll
                for (int j = 0; j < 4; j++)
                    #pragma unroll
                    for (int mt = 0; mt < 2; mt++) {
                        mma16816(acc[mt][j], ah[mt], bh[0][j]);
                        mma16816(acc[mt][j], al[mt], bh[0][j]);
                        mma16816(acc[mt][j], ah[mt], bl[0][j]);
                    }
            }
            // ---- half h=1: prefetch (kt+1, h=0) -> buf0, compute buf1 ----
            {
                if (kt + 1 < 16) {
                    int base = (kt + 1) * 2048 + lane;
                    #pragma unroll
                    for (int j = 0; j < 4; j++) {
                        bh[0][j] = g1h[base + j * 32];
                        bl[0][j] = g1l[base + j * 32];
                    }
                }
                #pragma unroll
                for (int j = 0; j < 4; j++)
                    #pragma unroll
                    for (int mt = 0; mt < 2; mt++) {
                        mma16816(acc[mt][4 + j], ah[mt], bh[1][j]);
                        mma16816(acc[mt][4 + j], al[mt], bh[1][j]);
                        mma16816(acc[mt][4 + j], ah[mt], bl[1][j]);
                    }
            }
        }
    }

    // ============ softmax (base-2, single block sync) ============
    float* lmaxs = (float*)(smem + OFF_LMAX);   // [32][8]
    float* lsums = (float*)(smem + OFF_LSUM);

    float lmax[2][2];
    #pragma unroll
    for (int mt = 0; mt < 2; mt++)
        #pragma unroll
        for (int i2 = 0; i2 < 2; i2++) {
            float m = -CUDART_INF_F;
            #pragma unroll
            for (int j = 0; j < 8; j++) {
                m = fmaxf(m, acc[mt][j][2 * i2]);
                m = fmaxf(m, acc[mt][j][2 * i2 + 1]);
            }
            m = fmaxf(m, __shfl_xor_sync(0xffffffffu, m, 1));
            m = fmaxf(m, __shfl_xor_sync(0xffffffffu, m, 2));
            lmax[mt][i2] = m;
            float s = 0.f;
            #pragma unroll
            for (int j = 0; j < 8; j++) {
                float e0 = ex2(acc[mt][j][2 * i2]     - m);
                float e1 = ex2(acc[mt][j][2 * i2 + 1] - m);
                acc[mt][j][2 * i2]     = e0;
                acc[mt][j][2 * i2 + 1] = e1;
                s += e0 + e1;
            }
            s += __shfl_xor_sync(0xffffffffu, s, 1);
            s += __shfl_xor_sync(0xffffffffu, s, 2);
            if (t == 0) {
                lmaxs[(mt * 16 + g + 8 * i2) * 8 + w] = m;
                lsums[(mt * 16 + g + 8 * i2) * 8 + w] = s;
            }
        }
    __syncthreads();

    float scale[2][2], inv[2][2];
    #pragma unroll
    for (int mt = 0; mt < 2; mt++)
        #pragma unroll
        for (int i2 = 0; i2 < 2; i2++) {
            int row = mt * 16 + g + 8 * i2;
            const float* Lm = &lmaxs[row * 8];
            const float* Ls = &lsums[row * 8];
            float gm = Lm[0];
            #pragma unroll
            for (int j = 1; j < 8; j++) gm = fmaxf(gm, Lm[j]);
            float gs = 0.f;
            #pragma unroll
            for (int j = 0; j < 8; j++) gs += Ls[j] * ex2(Lm[j] - gm);
            scale[mt][i2] = ex2(lmax[mt][i2] - gm) * 16384.f;
            inv[mt][i2] = 1.f / (gs * 16384.f);
        }

    // ---- pack P hi (scaled by 2^14 * warp-renorm) into GEMM2 A layout ----
    #pragma unroll
    for (int mt = 0; mt < 2; mt++)
        #pragma unroll
        for (int j = 0; j < 8; j++) {
            int kt2 = w * 4 + (j >> 1);
            int base = ((kt2 * 2 + mt) * 32 + (lane ^ (kt2 & 7))) * 16 + 8 * (j & 1);
            *(uint32_t*)(smem + OFF_PH + base)     = pack2h(acc[mt][j][0] * scale[mt][0],
                                                            acc[mt][j][1] * scale[mt][0]);
            *(uint32_t*)(smem + OFF_PH + base + 4) = pack2h(acc[mt][j][2] * scale[mt][1],
                                                            acc[mt][j][3] * scale[mt][1]);
        }
    __syncthreads();

    // ================= GEMM2: R = P @ M (32x256, warp = 32x32, 1-term) ============
    float a2[2][4][4];
    #pragma unroll
    for (int mt = 0; mt < 2; mt++)
        #pragma unroll
        for (int j = 0; j < 4; j++)
            #pragma unroll
            for (int i = 0; i < 4; i++) a2[mt][j][i] = 0.f;

    {
        const uint2* __restrict__ g2h = &G2B[memi][0][w * 4][0];
        // element (kt, j): kt*1024 + j*32 + lane
        uint2 ch[2][4];
        #pragma unroll
        for (int j = 0; j < 4; j++) ch[0][j] = g2h[j * 32 + lane];

        #pragma unroll 1
        for (int kp = 0; kp < 16; kp++) {
            // ---- kt = 2*kp (buf0), prefetch kt+1 -> buf1 ----
            {
                int kt = 2 * kp;
                uint4 ph[2];
                #pragma unroll
                for (int mt = 0; mt < 2; mt++) {
                    int chunk = ((kt * 2 + mt) * 32 + (lane ^ (kt & 7))) * 16;
                    ph[mt] = *(const uint4*)(smem + OFF_PH + chunk);
                }
                int base = (kt + 1) * 1024 + lane;
                #pragma unroll
                for (int j = 0; j < 4; j++) ch[1][j] = g2h[base + j * 32];
                #pragma unroll
                for (int j = 0; j < 4; j++)
                    #pragma unroll
                    for (int mt = 0; mt < 2; mt++)
                        mma16816(a2[mt][j], ph[mt], ch[0][j]);
            }
            // ---- kt = 2*kp+1 (buf1), prefetch kt+1 -> buf0 ----
            {
                int kt = 2 * kp + 1;
                uint4 ph[2];
                #pragma unroll
                for (int mt = 0; mt < 2; mt++) {
                    int chunk = ((kt * 2 + mt) * 32 + (lane ^ (kt & 7))) * 16;
                    ph[mt] = *(const uint4*)(smem + OFF_PH + chunk);
                }
                if (kt + 1 < 32) {
                    int base = (kt + 1) * 1024 + lane;
                    #pragma unroll
                    for (int j = 0; j < 4; j++) ch[0][j] = g2h[base + j * 32];
                }
                #pragma unroll
                for (int j = 0; j < 4; j++)
                    #pragma unroll
                    for (int mt = 0; mt < 2; mt++)
                        mma16816(a2[mt][j], ph[mt], ch[1][j]);
            }
        }
    }

    // ---- epilogue: scale by 1/(gsum*2^14), store R half (streaming) ----
    #pragma unroll
    for (int mt = 0; mt < 2; mt++)
        #pragma unroll
        for (int j = 0; j < 4; j++) {
            int col = w * 32 + j * 8 + 2 * t;
            #pragma unroll
            for (int i2 = 0; i2 < 2; i2++) {
                int gr = n0 + mt * 16 + g + 8 * i2;
                float2 o;
                o.x = a2[mt][j][2 * i2]     * inv[mt][i2];
                o.y = a2[mt][j][2 * i2 + 1] * inv[mt][i2];
                __stcs((float2*)&outg[(size_t)gr * 512 + 256 + col], o);
            }
        }
}

extern "C" void kernel_launch(void* const* d_in, const int* in_sizes, int n_in,
                              void* d_out, int out_size) {
    const float* query      = (const float*)d_in[0];
    const float* mem_attr   = (const float*)d_in[1];
    const float* mem_struct = (const float*)d_in[2];
    float* out = (float*)d_out;

    prep_kernel<<<512, 256>>>(mem_attr, mem_struct);

    cudaFuncSetAttribute(smgt_hmma, cudaFuncAttributeMaxDynamicSharedMemorySize, SMEM_BYTES);
    dim3 grid(N_TILES, 2);
    smgt_hmma<<<grid, THREADS, SMEM_BYTES>>>(query, out);
}

// round 16
// speedup vs baseline: 1.1951x; 1.0037x over previous
#include <cuda_runtime.h>
#include <cuda_fp16.h>
#include <math_constants.h>
#include <cstdint>

#define N_NODES 100000
#define D_MODEL 256
#define N_SLOTS 512
#define TILE_M 32
#define THREADS 256
#define N_TILES (N_NODES / TILE_M)   // 3125 exactly
#define LOG2E_F 1.4426950408889634f

// smem byte offsets
#define OFF_QH 0          // 16KB  (GEMM1 A hi)
#define OFF_QL 16384      // 16KB  (GEMM1 A lo)
#define OFF_PH 0          // 32KB  (GEMM2 A hi — overlays QH+QL)
#define OFF_LMAX 32768    // 1KB [32][8]
#define OFF_LSUM 33792    // 1KB
#define SMEM_BYTES 34816

// Pre-packed B fragments for mma.sync.m16n8k16.row.col (4 halfs per lane, uint2).
// G1B[mem][split][kt(16)][nt(64)][lane(32)] : B = (M*log2e)^T  (k=dmodel, n=slot)
// G2B[mem][kt(32)][nt(32)][lane(32)]        : B = M hi         (k=slot,  n=dmodel)
__device__ __align__(16) uint2 G1B[2][2][16][64][32];
__device__ __align__(16) uint2 G2B[2][32][32][32];

__device__ __forceinline__ void split2h(float x, float y, uint32_t& hi, uint32_t& lo) {
    __half hx = __float2half_rn(x);
    __half hy = __float2half_rn(y);
    __half lx = __float2half_rn(x - __half2float(hx));
    __half ly = __float2half_rn(y - __half2float(hy));
    __half2 h = __halves2half2(hx, hy);
    __half2 l = __halves2half2(lx, ly);
    hi = *(uint32_t*)&h;
    lo = *(uint32_t*)&l;
}

__device__ __forceinline__ uint32_t pack2h(float x, float y) {
    __half2 h = __halves2half2(__float2half_rn(x), __float2half_rn(y));
    return *(uint32_t*)&h;
}

__device__ __forceinline__ float ex2(float x) {
    float r;
    asm("ex2.approx.f32 %0, %1;" : "=f"(r) : "f"(x));
    return r;
}

// L2-only (L1-bypass) uint2 load for streaming B fragments
__device__ __forceinline__ uint2 ldcg2(const uint2* p) {
    uint2 v;
    asm volatile("ld.global.cg.v2.u32 {%0, %1}, [%2];"
                 : "=r"(v.x), "=r"(v.y) : "l"(p));
    return v;
}

__device__ __forceinline__ void mma16816(float* c, const uint4& a, const uint2& b) {
    asm volatile(
        "mma.sync.aligned.m16n8k16.row.col.f32.f16.f16.f32 "
        "{%0,%1,%2,%3}, {%4,%5,%6,%7}, {%8,%9}, {%0,%1,%2,%3};"
        : "+f"(c[0]), "+f"(c[1]), "+f"(c[2]), "+f"(c[3])
        : "r"(a.x), "r"(a.y), "r"(a.z), "r"(a.w), "r"(b.x), "r"(b.y));
}

// ---------------- prep: pack memory matrices into B-fragment order ----------------
__global__ void prep_kernel(const float* __restrict__ ma, const float* __restrict__ ms) {
    int idx = blockIdx.x * blockDim.x + threadIdx.x;
    if (idx >= 131072) return;
    bool isG2 = idx >= 65536;
    int r = idx & 65535;
    int lane = r & 31;
    int t = lane & 3, g = lane >> 2;
    if (!isG2) {
        int nt = (r >> 5) & 63;
        int kt = (r >> 11) & 15;
        int mem = (r >> 15) & 1;
        const float* src = mem ? ms : ma;
        int slot = nt * 8 + g;
        int k = kt * 16 + 2 * t;
        float v0 = src[slot * D_MODEL + k]     * LOG2E_F;
        float v1 = src[slot * D_MODEL + k + 1] * LOG2E_F;
        float v2 = src[slot * D_MODEL + k + 8] * LOG2E_F;
        float v3 = src[slot * D_MODEL + k + 9] * LOG2E_F;
        uint32_t h01, l01, h23, l23;
        split2h(v0, v1, h01, l01);
        split2h(v2, v3, h23, l23);
        G1B[mem][0][kt][nt][lane] = make_uint2(h01, h23);
        G1B[mem][1][kt][nt][lane] = make_uint2(l01, l23);
    } else {
        int nt = (r >> 5) & 31;
        int kt = (r >> 10) & 31;
        int mem = (r >> 15) & 1;
        const float* src = mem ? ms : ma;
        int col = nt * 8 + g;
        int ks = kt * 16 + 2 * t;
        float v0 = src[(ks)     * D_MODEL + col];
        float v1 = src[(ks + 1) * D_MODEL + col];
        float v2 = src[(ks + 8) * D_MODEL + col];
        float v3 = src[(ks + 9) * D_MODEL + col];
        G2B[mem][kt][nt][lane] = make_uint2(pack2h(v0, v1), pack2h(v2, v3));
    }
}

// ---------------- main fused kernel (2 CTAs/SM, 8 warps each) ----------------
__global__ __launch_bounds__(THREADS, 2)
void smgt_hmma(const float* __restrict__ query, float* __restrict__ out) {
    extern __shared__ char smem[];
    const int tid = threadIdx.x;
    const int w = tid >> 5, lane = tid & 31;
    const int t = lane & 3, g = lane >> 2;
    const int memi = blockIdx.y;
    const int n0 = blockIdx.x * TILE_M;
    float* __restrict__ outg = out + (size_t)memi * N_NODES * 512u;

    // ---- load Q tile, split fp16 hi/lo, store A-fragment-packed; fuse Q-copy out ----
    #pragma unroll 4
    for (int it = 0; it < 8; it++) {
        int idx = tid + it * THREADS;    // 0..2047 float4s
        int rr = idx >> 6;               // row 0..31
        int c4 = idx & 63;
        int gr = n0 + rr;                // always < N_NODES (3125*32 = 100000)
        float4 v = ((const float4*)query)[(size_t)gr * 64 + c4];
        __stcs(((float4*)outg) + (size_t)gr * 128 + c4, v);   // Q copy (streaming)
        int mt = rr >> 4, sr = rr & 15, gg = sr & 7, hr = sr >> 3;
        #pragma unroll
        for (int p = 0; p < 2; p++) {
            int k = c4 * 4 + 2 * p;
            int kt = k >> 4, sk = k & 15;
            int ln = gg * 4 + ((sk & 7) >> 1);
            int off = ((kt * 2 + mt) * 32 + (ln ^ (kt & 7))) * 16 + 4 * hr + 8 * (sk >> 3);
            float x = p ? v.z : v.x;
            float y = p ? v.w : v.y;
            uint32_t hi, lo;
            split2h(x, y, hi, lo);
            *(uint32_t*)(smem + OFF_QH + off) = hi;
            *(uint32_t*)(smem + OFF_QL + off) = lo;
        }
    }
    __syncthreads();

    // ================= GEMM1: S' = Q @ (M*log2e)^T (32x512, warp = 32x64) ==========
    float acc[2][8][4];
    #pragma unroll
    for (int mt = 0; mt < 2; mt++)
        #pragma unroll
        for (int j = 0; j < 8; j++)
            #pragma unroll
            for (int i = 0; i < 4; i++) acc[mt][j][i] = 0.f;

    {
        const uint2* __restrict__ g1h = &G1B[memi][0][0][w * 8][0];
        const uint2* __restrict__ g1l = &G1B[memi][1][0][w * 8][0];
        // element (kt, h, j): kt*2048 + (h*4+j)*32 + lane   (uint2 units)
        uint2 bh[2][4], bl[2][4];
        #pragma unroll
        for (int j = 0; j < 4; j++) {
            bh[0][j] = ldcg2(g1h + j * 32 + lane);
            bl[0][j] = ldcg2(g1l + j * 32 + lane);
        }

        #pragma unroll 1
        for (int kt = 0; kt < 16; kt++) {
            uint4 ah[2], al[2];
            #pragma unroll
            for (int mt = 0; mt < 2; mt++) {
                int chunk = ((kt * 2 + mt) * 32 + (lane ^ (kt & 7))) * 16;
                ah[mt] = *(const uint4*)(smem + OFF_QH + chunk);
                al[mt] = *(const uint4*)(smem + OFF_QL + chunk);
            }

            // ---- half h=0: prefetch (kt, h=1) -> buf1, compute buf0 ----
            {
                int base = kt * 2048 + 128 + lane;
                #pragma unroll
                for (int j = 0; j < 4; j++) {
                    bh[1][j] = ldcg2(g1h + base + j * 32);
                    bl[1][j] = ldcg2(g1l + base + j * 32);
                }
                #pragma unroll
                for (int j = 0; j < 4; j++)
                    #pragma unroll
                    for (int mt = 0; mt < 2; mt++) {
                        mma16816(acc[mt][j], ah[mt], bh[0][j]);
                        mma16816(acc[mt][j], al[mt], bh[0][j]);
                        mma16816(acc[mt][j], ah[mt], bl[0][j]);
                    }
            }
            // ---- half h=1: prefetch (kt+1, h=0) -> buf0, compute buf1 ----
            {
                if (kt + 1 < 16) {
                    int base = (kt + 1) * 2048 + lane;
                    #pragma unroll
                    for (int j = 0; j < 4; j++) {
                        bh[0][j] = ldcg2(g1h + base + j * 32);
                        bl[0][j] = ldcg2(g1l + base + j * 32);
                    }
                }
                #pragma unroll
                for (int j = 0; j < 4; j++)
                    #pragma unroll
                    for (int mt = 0; mt < 2; mt++) {
                        mma16816(acc[mt][4 + j], ah[mt], bh[1][j]);
                        mma16816(acc[mt][4 + j], al[mt], bh[1][j]);
                        mma16816(acc[mt][4 + j], ah[mt], bl[1][j]);
                    }
            }
        }
    }

    // ============ softmax (base-2, single block sync) ============
    float* lmaxs = (float*)(smem + OFF_LMAX);   // [32][8]
    float* lsums = (float*)(smem + OFF_LSUM);

    float lmax[2][2];
    #pragma unroll
    for (int mt = 0; mt < 2; mt++)
        #pragma unroll
        for (int i2 = 0; i2 < 2; i2++) {
            float m = -CUDART_INF_F;
            #pragma unroll
            for (int j = 0; j < 8; j++) {
                m = fmaxf(m, acc[mt][j][2 * i2]);
                m = fmaxf(m, acc[mt][j][2 * i2 + 1]);
            }
            m = fmaxf(m, __shfl_xor_sync(0xffffffffu, m, 1));
            m = fmaxf(m, __shfl_xor_sync(0xffffffffu, m, 2));
            lmax[mt][i2] = m;
            float s = 0.f;
            #pragma unroll
            for (int j = 0; j < 8; j++) {
                float e0 = ex2(acc[mt][j][2 * i2]     - m);
                float e1 = ex2(acc[mt][j][2 * i2 + 1] - m);
                acc[mt][j][2 * i2]     = e0;
                acc[mt][j][2 * i2 + 1] = e1;
                s += e0 + e1;
            }
            s += __shfl_xor_sync(0xffffffffu, s, 1);
            s += __shfl_xor_sync(0xffffffffu, s, 2);
            if (t == 0) {
                lmaxs[(mt * 16 + g + 8 * i2) * 8 + w] = m;
                lsums[(mt * 16 + g + 8 * i2) * 8 + w] = s;
            }
        }
    __syncthreads();

    float scale[2][2], inv[2][2];
    #pragma unroll
    for (int mt = 0; mt < 2; mt++)
        #pragma unroll
        for (int i2 = 0; i2 < 2; i2++) {
            int row = mt * 16 + g + 8 * i2;
            const float* Lm = &lmaxs[row * 8];
            const float* Ls = &lsums[row * 8];
            float gm = Lm[0];
            #pragma unroll
            for (int j = 1; j < 8; j++) gm = fmaxf(gm, Lm[j]);
            float gs = 0.f;
            #pragma unroll
            for (int j = 0; j < 8; j++) gs += Ls[j] * ex2(Lm[j] - gm);
            scale[mt][i2] = ex2(lmax[mt][i2] - gm) * 16384.f;
            inv[mt][i2] = 1.f / (gs * 16384.f);
        }

    // ---- pack P hi (scaled by 2^14 * warp-renorm) into GEMM2 A layout ----
    #pragma unroll
    for (int mt = 0; mt < 2; mt++)
        #pragma unroll
        for (int j = 0; j < 8; j++) {
            int kt2 = w * 4 + (j >> 1);
            int base = ((kt2 * 2 + mt) * 32 + (lane ^ (kt2 & 7))) * 16 + 8 * (j & 1);
            *(uint32_t*)(smem + OFF_PH + base)     = pack2h(acc[mt][j][0] * scale[mt][0],
                                                            acc[mt][j][1] * scale[mt][0]);
            *(uint32_t*)(smem + OFF_PH + base + 4) = pack2h(acc[mt][j][2] * scale[mt][1],
                                                            acc[mt][j][3] * scale[mt][1]);
        }
    __syncthreads();

    // ================= GEMM2: R = P @ M (32x256, warp = 32x32, 1-term) ============
    float a2[2][4][4];
    #pragma unroll
    for (int mt = 0; mt < 2; mt++)
        #pragma unroll
        for (int j = 0; j < 4; j++)
            #pragma unroll
            for (int i = 0; i < 4; i++) a2[mt][j][i] = 0.f;

    {
        const uint2* __restrict__ g2h = &G2B[memi][0][w * 4][0];
        // element (kt, j): kt*1024 + j*32 + lane
        uint2 ch[2][4];
        #pragma unroll
        for (int j = 0; j < 4; j++) ch[0][j] = ldcg2(g2h + j * 32 + lane);

        #pragma unroll 1
        for (int kp = 0; kp < 16; kp++) {
            // ---- kt = 2*kp (buf0), prefetch kt+1 -> buf1 ----
            {
                int kt = 2 * kp;
                uint4 ph[2];
                #pragma unroll
                for (int mt = 0; mt < 2; mt++) {
                    int chunk = ((kt * 2 + mt) * 32 + (lane ^ (kt & 7))) * 16;
                    ph[mt] = *(const uint4*)(smem + OFF_PH + chunk);
                }
                int base = (kt + 1) * 1024 + lane;
                #pragma unroll
                for (int j = 0; j < 4; j++) ch[1][j] = ldcg2(g2h + base + j * 32);
                #pragma unroll
                for (int j = 0; j < 4; j++)
                    #pragma unroll
                    for (int mt = 0; mt < 2; mt++)
                        mma16816(a2[mt][j], ph[mt], ch[0][j]);
            }
            // ---- kt = 2*kp+1 (buf1), prefetch kt+1 -> buf0 ----
            {
                int kt = 2 * kp + 1;
                uint4 ph[2];
                #pragma unroll
                for (int mt = 0; mt < 2; mt++) {
                    int chunk = ((kt * 2 + mt) * 32 + (lane ^ (kt & 7))) * 16;
                    ph[mt] = *(const uint4*)(smem + OFF_PH + chunk);
                }
                if (kt + 1 < 32) {
                    int base = (kt + 1) * 1024 + lane;
                    #pragma unroll
                    for (int j = 0; j < 4; j++) ch[0][j] = ldcg2(g2h + base + j * 32);
                }
                #pragma unroll
                for (int j = 0; j < 4; j++)
                    #pragma unroll
                    for (int mt = 0; mt < 2; mt++)
                        mma16816(a2[mt][j], ph[mt], ch[1][j]);
            }
        }
    }

    // ---- epilogue: scale by 1/(gsum*2^14), store R half (streaming) ----
    #pragma unroll
    for (int mt = 0; mt < 2; mt++)
        #pragma unroll
        for (int j = 0; j < 4; j++) {
            int col = w * 32 + j * 8 + 2 * t;
            #pragma unroll
            for (int i2 = 0; i2 < 2; i2++) {
                int gr = n0 + mt * 16 + g + 8 * i2;
                float2 o;
                o.x = a2[mt][j][2 * i2]     * inv[mt][i2];
                o.y = a2[mt][j][2 * i2 + 1] * inv[mt][i2];
                __stcs((float2*)&outg[(size_t)gr * 512 + 256 + col], o);
            }
        }
}

extern "C" void kernel_launch(void* const* d_in, const int* in_sizes, int n_in,
                              void* d_out, int out_size) {
    const float* query      = (const float*)d_in[0];
    const float* mem_attr   = (const float*)d_in[1];
    const float* mem_struct = (const float*)d_in[2];
    float* out = (float*)d_out;

    prep_kernel<<<512, 256>>>(mem_attr, mem_struct);

    cudaFuncSetAttribute(smgt_hmma, cudaFuncAttributeMaxDynamicSharedMemorySize, SMEM_BYTES);
    dim3 grid(N_TILES, 2);
    smgt_hmma<<<grid, THREADS, SMEM_BYTES>>>(query, out);
}